// round 5
// baseline (speedup 1.0000x reference)
#include <cuda_runtime.h>
#include <cstddef>

// ---------------------------------------------------------------------------
// Problem constants
// ---------------------------------------------------------------------------
#define HH 384
#define WW 384
#define BB 2
#define NFC 64
#define COUTF 35   // output conv channels (sum of SECTIONS = 2+3+4+5+6+7+8 = 35)

// Scratch activations (allocation-free rule: __device__ globals)
__device__ float g_bufA[(size_t)BB * NFC * HH * WW];
__device__ float g_bufB[(size_t)BB * NFC * HH * WW];
__device__ float g_core[(size_t)BB * COUTF * HH * WW];

// ---------------------------------------------------------------------------
// 3x3 SAME conv (cross-correlation, NCHW / OIHW), optional ReLU / residual.
// Block 512 = 32 column-pair threads x 16 co-groups. 1 block/SM.
// Tile: 64 cols x 4 rows x COUT channels. Per thread: 4 co x 4 rows x 2 cols.
// ALL weights staged to smem ONCE per block, layout [ci][tap][co] so one
// broadcast LDS.128 fetches the 4 co weights for a tap.
// Input chunked CB channels at a time (6 rows x 66 cols + stride pad).
// ---------------------------------------------------------------------------
template<int CIN, int CB, int COUT, bool RELU, bool RESID>
__global__ __launch_bounds__(512, 1)
void conv3x3(const float* __restrict__ in, const float* __restrict__ wgt,
             const float* __restrict__ bias, const float* __restrict__ res,
             float* __restrict__ out)
{
    constexpr int COPAD = (COUT + 3) / 4 * 4;
    extern __shared__ float smem[];
    float* sW  = smem;                          // [CIN][9][COPAD]
    float* sIn = smem + CIN * 9 * COPAD;        // [CB][6][68]

    const int t  = threadIdx.x;
    const int tp = t & 31;               // column-pair index (cols 2tp, 2tp+1)
    const int tc = t >> 5;               // co group (0..15): co 4tc..4tc+3
    const int x0 = blockIdx.x * 64;
    const int y0 = blockIdx.y * 4;
    const int b  = blockIdx.z;
    const bool active = (4 * tc) < COUT;

    // --- stage ALL weights once: wgt[co][ci][tap] -> sW[ci][tap][co] ---
    const int NWT = COUT * CIN * 9;
    for (int idx = t; idx < NWT; idx += 512) {
        int co  = idx / (CIN * 9);
        int rem = idx - co * (CIN * 9);
        int ci  = rem / 9;
        int tap = rem - ci * 9;
        sW[(ci * 9 + tap) * COPAD + co] = wgt[idx];
    }

    float acc[4][4][2];                  // [co][row][col]
    #pragma unroll
    for (int i = 0; i < 4; ++i) {
        int co = 4 * tc + i;
        float bv = (co < COUT) ? bias[co] : 0.f;
        #pragma unroll
        for (int ro = 0; ro < 4; ++ro) { acc[i][ro][0] = bv; acc[i][ro][1] = bv; }
    }

    for (int cb = 0; cb < CIN; cb += CB) {
        __syncthreads();
        // --- stage input tile (CB x 6 x 66 used, stride 68), zero-padded ---
        const int NIN = CB * 6 * 68;
        for (int idx = t; idx < NIN; idx += 512) {
            int ci  = idx / 408;
            int rem = idx - ci * 408;
            int ry  = rem / 68;
            int s   = rem - ry * 68;
            int gy  = y0 - 1 + ry;
            int gx  = x0 + s - 1;
            float v = 0.f;
            if (s < 66 && gy >= 0 && gy < HH && gx >= 0 && gx < WW)
                v = in[(((size_t)b * CIN + cb + ci) * HH + gy) * WW + gx];
            sIn[(ci * 6 + ry) * 68 + s] = v;
        }
        __syncthreads();

        if (active) {
            #pragma unroll 1
            for (int ci = 0; ci < CB; ++ci) {
                // 6 rows x 4 cols (2tp..2tp+3 halo coords): two LDS.64 per row
                float x[6][4];
                #pragma unroll
                for (int r = 0; r < 6; ++r) {
                    const float2* rp = (const float2*)&sIn[(ci * 6 + r) * 68];
                    float2 a = rp[tp];
                    float2 c = rp[tp + 1];
                    x[r][0] = a.x; x[r][1] = a.y; x[r][2] = c.x; x[r][3] = c.y;
                }
                const float* wb = &sW[(cb + ci) * 9 * COPAD];
                #pragma unroll
                for (int ky = 0; ky < 3; ++ky)
                    #pragma unroll
                    for (int kx = 0; kx < 3; ++kx) {
                        float4 wv = *(const float4*)&wb[(ky * 3 + kx) * COPAD + 4 * tc];
                        #pragma unroll
                        for (int ro = 0; ro < 4; ++ro) {
                            float xa = x[ro + ky][kx];
                            float xb = x[ro + ky][kx + 1];
                            acc[0][ro][0] += wv.x * xa;  acc[0][ro][1] += wv.x * xb;
                            acc[1][ro][0] += wv.y * xa;  acc[1][ro][1] += wv.y * xb;
                            acc[2][ro][0] += wv.z * xa;  acc[2][ro][1] += wv.z * xb;
                            acc[3][ro][0] += wv.w * xa;  acc[3][ro][1] += wv.w * xb;
                        }
                    }
            }
        }
    }

    if (active) {
        #pragma unroll
        for (int i = 0; i < 4; ++i) {
            int co = 4 * tc + i;
            if (co >= COUT) break;
            #pragma unroll
            for (int ro = 0; ro < 4; ++ro) {
                size_t oi = (((size_t)b * COUT + co) * HH + (y0 + ro)) * WW + (x0 + 2 * tp);
                float v0 = acc[i][ro][0], v1 = acc[i][ro][1];
                if (RELU) { v0 = fmaxf(v0, 0.f); v1 = fmaxf(v1, 0.f); }
                if (RESID) {
                    float2 rv = *(const float2*)&res[oi];
                    v0 += rv.x; v1 += rv.y;
                }
                float2 ov; ov.x = v0; ov.y = v1;
                *(float2*)&out[oi] = ov;
            }
        }
    }
}

// ---------------------------------------------------------------------------
// KPN aggregation. Radial interpolation tables are computed at COMPILE TIME
// so all channel indices are immediates -> core channels live in registers.
// ---------------------------------------------------------------------------
#define FST 33   // frame tile smem stride
#define FTH 30   // frame tile extent: 16 + 2*7

struct TEnt { int lo, hi, doff; bool inR; float a, b; };

__host__ __device__ constexpr double csqrt_(double x) {
    double g = x > 1.0 ? x : 1.0;
    for (int i = 0; i < 100; ++i) g = 0.5 * (g + x / g);
    return g;
}

__host__ __device__ constexpr TEnt tentry(int w, int p) {
    const int K = 2 * w - 1;
    const int r = w - 1;
    const int coff = w * (w - 1) / 2 - 1;   // 0,2,5,9,14,20,27
    const int i = p / K, j = p % K;
    TEnt e{};
    e.doff = (i - r) * FST + (j - r);
    const int s2 = (i - r) * (i - r) + (j - r) * (j - r);
    int q = 0;
    while ((q + 1) * (q + 1) <= s2) ++q;
    if (q * q == s2) {
        if (q > r) { e.inR = false; e.lo = coff; e.hi = coff; e.a = 0.f; e.b = 0.f; }
        else       { e.inR = true;  e.lo = coff + q; e.hi = coff + q; e.a = 1.f; e.b = 0.f; }
    } else {
        if (q >= r) { e.inR = false; e.lo = coff; e.hi = coff; e.a = 0.f; e.b = 0.f; }
        else {
            double d = csqrt_((double)s2);
            e.inR = true;
            e.lo = coff + q;
            e.hi = coff + q + 1;
            e.a = (float)((double)(q + 1) - d);
            e.b = (float)(d - (double)q);
        }
    }
    return e;
}

// Divide-and-conquer tap expansion: recursion depth O(log2 N).
template<int W, int Lo, int N>
struct KLoop {
    static __device__ __forceinline__ void run(const float (&c)[COUTF],
                                               const float* __restrict__ sF,
                                               int center, float& den, float& num) {
        KLoop<W, Lo, N / 2>::run(c, sF, center, den, num);
        KLoop<W, Lo + N / 2, N - N / 2>::run(c, sF, center, den, num);
    }
};

template<int W, int Lo>
struct KLoop<W, Lo, 1> {
    static __device__ __forceinline__ void run(const float (&c)[COUTF],
                                               const float* __restrict__ sF,
                                               int center, float& den, float& num) {
        constexpr TEnt e = tentry(W, Lo);
        float patch = sF[center + e.doff];
        if constexpr (e.inR) {
            float v = e.a * c[e.lo] + e.b * c[e.hi];
            float tt = __expf(v);
            den += tt;
            num += tt * patch;
        } else {
            den += 1.f;     // exp(0)
            num += patch;
        }
    }
};

template<int W, int Lo>
struct KLoop<W, Lo, 0> {
    static __device__ __forceinline__ void run(const float (&)[COUTF],
                                               const float* __restrict__,
                                               int, float&, float&) {}
};

template<int W>
__device__ __forceinline__ float section_run(const float (&c)[COUTF],
                                             const float* __restrict__ sF, int center) {
    constexpr int K = 2 * W - 1;
    float den = 0.f, num = 0.f;
    KLoop<W, 0, K * K>::run(c, sF, center, den, num);
    return num / den;
}

__global__ __launch_bounds__(256)
void kpn_kernel(const float* __restrict__ core, const float* __restrict__ data,
                float* __restrict__ out)
{
    __shared__ float sF[FTH * FST];
    const int t  = threadIdx.x;
    const int tx = t & 15, ty = t >> 4;
    const int bx = blockIdx.x, by = blockIdx.y, b = blockIdx.z;
    const int x  = bx * 16 + tx, y = by * 16 + ty;
    const int oy = by * 16 - 7,  ox = bx * 16 - 7;

    for (int idx = t; idx < FTH * FTH; idx += 256) {
        int fy = idx / FTH, fx = idx - fy * FTH;
        int gy = oy + fy,   gx = ox + fx;
        float v = 0.f;
        if (gy >= 0 && gy < HH && gx >= 0 && gx < WW)
            v = data[((size_t)b * HH + gy) * WW + gx];
        sF[fy * FST + fx] = v;
    }
    __syncthreads();

    float c[COUTF];
    #pragma unroll
    for (int ch = 0; ch < COUTF; ++ch)
        c[ch] = fabsf(core[(((size_t)b * COUTF + ch) * HH + y) * WW + x]);

    const int center = (ty + 7) * FST + (tx + 7);
    float pred = 0.f;
    pred += section_run<2>(c, sF, center);
    pred += section_run<3>(c, sF, center);
    pred += section_run<4>(c, sF, center);
    pred += section_run<5>(c, sF, center);
    pred += section_run<6>(c, sF, center);
    pred += section_run<7>(c, sF, center);
    pred += section_run<8>(c, sF, center);

    out[((size_t)b * HH + y) * WW + x] = pred;
}

// ---------------------------------------------------------------------------
// Launch
// ---------------------------------------------------------------------------
static inline int smem_bytes(int cin, int cb, int cout) {
    int copad = (cout + 3) / 4 * 4;
    return (cin * 9 * copad + cb * 6 * 68) * 4;
}

extern "C" void kernel_launch(void* const* d_in, const int* in_sizes, int n_in,
                              void* d_out, int out_size) {
    (void)in_sizes; (void)n_in; (void)out_size;
    const float* data_with_est = (const float*)d_in[0];
    const float* data    = (const float*)d_in[1];
    const float* w_first = (const float*)d_in[2];
    const float* b_first = (const float*)d_in[3];
    const float* w1a = (const float*)d_in[4];
    const float* b1a = (const float*)d_in[5];
    const float* w1b = (const float*)d_in[6];
    const float* b1b = (const float*)d_in[7];
    const float* w2a = (const float*)d_in[8];
    const float* b2a = (const float*)d_in[9];
    const float* w2b = (const float*)d_in[10];
    const float* b2b = (const float*)d_in[11];
    const float* w3a = (const float*)d_in[12];
    const float* b3a = (const float*)d_in[13];
    const float* w3b = (const float*)d_in[14];
    const float* b3b = (const float*)d_in[15];
    const float* w_out = (const float*)d_in[16];
    const float* b_out = (const float*)d_in[17];
    float* out = (float*)d_out;

    float *A = nullptr, *Bb = nullptr, *core = nullptr;
    cudaGetSymbolAddress((void**)&A, g_bufA);
    cudaGetSymbolAddress((void**)&Bb, g_bufB);
    cudaGetSymbolAddress((void**)&core, g_core);

    const int smFirst = smem_bytes(2, 2, NFC);
    const int smMain  = smem_bytes(NFC, 8, NFC);
    const int smOut   = smem_bytes(NFC, 8, COUTF);

    static bool attrSet = false;
    if (!attrSet) {
        cudaFuncSetAttribute(conv3x3<2, 2, NFC, false, false>,
                             cudaFuncAttributeMaxDynamicSharedMemorySize, smFirst);
        cudaFuncSetAttribute(conv3x3<NFC, 8, NFC, true, false>,
                             cudaFuncAttributeMaxDynamicSharedMemorySize, smMain);
        cudaFuncSetAttribute(conv3x3<NFC, 8, NFC, false, true>,
                             cudaFuncAttributeMaxDynamicSharedMemorySize, smMain);
        cudaFuncSetAttribute(conv3x3<NFC, 8, COUTF, false, false>,
                             cudaFuncAttributeMaxDynamicSharedMemorySize, smOut);
        attrSet = true;
    }

    dim3 cgrid(WW / 64, HH / 4, BB), cblk(512);

    // first conv: 2 -> 64, no relu
    conv3x3<2, 2, NFC, false, false><<<cgrid, cblk, smFirst>>>(data_with_est, w_first, b_first, nullptr, A);
    // resblock 1
    conv3x3<NFC, 8, NFC, true,  false><<<cgrid, cblk, smMain>>>(A,  w1a, b1a, nullptr, Bb);
    conv3x3<NFC, 8, NFC, false, true ><<<cgrid, cblk, smMain>>>(Bb, w1b, b1b, A, A);
    // resblock 2
    conv3x3<NFC, 8, NFC, true,  false><<<cgrid, cblk, smMain>>>(A,  w2a, b2a, nullptr, Bb);
    conv3x3<NFC, 8, NFC, false, true ><<<cgrid, cblk, smMain>>>(Bb, w2b, b2b, A, A);
    // resblock 3
    conv3x3<NFC, 8, NFC, true,  false><<<cgrid, cblk, smMain>>>(A,  w3a, b3a, nullptr, Bb);
    conv3x3<NFC, 8, NFC, false, true ><<<cgrid, cblk, smMain>>>(Bb, w3b, b3b, A, A);
    // output conv: 64 -> 35
    conv3x3<NFC, 8, COUTF, false, false><<<cgrid, cblk, smOut>>>(A, w_out, b_out, nullptr, core);

    // KPN aggregation
    kpn_kernel<<<dim3(WW / 16, HH / 16, BB), 256>>>(core, data, out);
}

// round 6
// speedup vs baseline: 1.5563x; 1.5563x over previous
#include <cuda_runtime.h>
#include <cstddef>

// ---------------------------------------------------------------------------
// Problem constants
// ---------------------------------------------------------------------------
#define HH 384
#define WW 384
#define BB 2
#define NFC 64
#define COUTF 35   // output conv channels (sum of SECTIONS = 2+3+4+5+6+7+8 = 35)

// Scratch activations (allocation-free rule: __device__ globals)
__device__ float g_bufA[(size_t)BB * NFC * HH * WW];
__device__ float g_bufB[(size_t)BB * NFC * HH * WW];
__device__ float g_core[(size_t)BB * COUTF * HH * WW];

// ---------------------------------------------------------------------------
// 3x3 SAME conv (cross-correlation, NCHW / OIHW), optional ReLU / residual.
// Block 512 = 32 column-pair threads x 16 co-groups. 1 block/SM.
// Tile: 64 cols x 4 rows x COUT channels. Per thread: 4 co x 4 rows x 2 cols.
// ALL weights staged to smem ONCE per block, layout [ci][tap][co] so one
// broadcast LDS.128 fetches the 4 co weights for a tap.
// Input chunked CB channels at a time (6 rows x 66 cols + stride pad).
// ---------------------------------------------------------------------------
template<int CIN, int CB, int COUT, bool RELU, bool RESID>
__global__ __launch_bounds__(512, 1)
void conv3x3(const float* __restrict__ in, const float* __restrict__ wgt,
             const float* __restrict__ bias, const float* __restrict__ res,
             float* __restrict__ out)
{
    constexpr int COPAD = (COUT + 3) / 4 * 4;
    extern __shared__ float smem[];
    float* sW  = smem;                          // [CIN][9][COPAD]
    float* sIn = smem + CIN * 9 * COPAD;        // [CB][6][68]

    const int t  = threadIdx.x;
    const int tp = t & 31;               // column-pair index (cols 2tp, 2tp+1)
    const int tc = t >> 5;               // co group (0..15): co 4tc..4tc+3
    const int x0 = blockIdx.x * 64;
    const int y0 = blockIdx.y * 4;
    const int b  = blockIdx.z;
    const bool active = (4 * tc) < COUT;

    // --- stage ALL weights once: wgt[co][ci][tap] -> sW[ci][tap][co] ---
    const int NWT = COUT * CIN * 9;
    for (int idx = t; idx < NWT; idx += 512) {
        int co  = idx / (CIN * 9);
        int rem = idx - co * (CIN * 9);
        int ci  = rem / 9;
        int tap = rem - ci * 9;
        sW[(ci * 9 + tap) * COPAD + co] = wgt[idx];
    }

    float acc[4][4][2];                  // [co][row][col]
    #pragma unroll
    for (int i = 0; i < 4; ++i) {
        int co = 4 * tc + i;
        float bv = (co < COUT) ? bias[co] : 0.f;
        #pragma unroll
        for (int ro = 0; ro < 4; ++ro) { acc[i][ro][0] = bv; acc[i][ro][1] = bv; }
    }

    for (int cb = 0; cb < CIN; cb += CB) {
        __syncthreads();
        // --- stage input tile (CB x 6 x 66 used, stride 68), zero-padded ---
        const int NIN = CB * 6 * 68;
        for (int idx = t; idx < NIN; idx += 512) {
            int ci  = idx / 408;
            int rem = idx - ci * 408;
            int ry  = rem / 68;
            int s   = rem - ry * 68;
            int gy  = y0 - 1 + ry;
            int gx  = x0 + s - 1;
            float v = 0.f;
            if (s < 66 && gy >= 0 && gy < HH && gx >= 0 && gx < WW)
                v = in[(((size_t)b * CIN + cb + ci) * HH + gy) * WW + gx];
            sIn[(ci * 6 + ry) * 68 + s] = v;
        }
        __syncthreads();

        if (active) {
            #pragma unroll 1
            for (int ci = 0; ci < CB; ++ci) {
                // 6 rows x 4 cols (2tp..2tp+3 halo coords): two LDS.64 per row
                float x[6][4];
                #pragma unroll
                for (int r = 0; r < 6; ++r) {
                    const float2* rp = (const float2*)&sIn[(ci * 6 + r) * 68];
                    float2 a = rp[tp];
                    float2 c = rp[tp + 1];
                    x[r][0] = a.x; x[r][1] = a.y; x[r][2] = c.x; x[r][3] = c.y;
                }
                const float* wb = &sW[(cb + ci) * 9 * COPAD];
                #pragma unroll
                for (int ky = 0; ky < 3; ++ky)
                    #pragma unroll
                    for (int kx = 0; kx < 3; ++kx) {
                        float4 wv = *(const float4*)&wb[(ky * 3 + kx) * COPAD + 4 * tc];
                        #pragma unroll
                        for (int ro = 0; ro < 4; ++ro) {
                            float xa = x[ro + ky][kx];
                            float xb = x[ro + ky][kx + 1];
                            acc[0][ro][0] += wv.x * xa;  acc[0][ro][1] += wv.x * xb;
                            acc[1][ro][0] += wv.y * xa;  acc[1][ro][1] += wv.y * xb;
                            acc[2][ro][0] += wv.z * xa;  acc[2][ro][1] += wv.z * xb;
                            acc[3][ro][0] += wv.w * xa;  acc[3][ro][1] += wv.w * xb;
                        }
                    }
            }
        }
    }

    if (active) {
        #pragma unroll
        for (int i = 0; i < 4; ++i) {
            int co = 4 * tc + i;
            if (co >= COUT) break;
            #pragma unroll
            for (int ro = 0; ro < 4; ++ro) {
                size_t oi = (((size_t)b * COUT + co) * HH + (y0 + ro)) * WW + (x0 + 2 * tp);
                float v0 = acc[i][ro][0], v1 = acc[i][ro][1];
                if (RELU) { v0 = fmaxf(v0, 0.f); v1 = fmaxf(v1, 0.f); }
                if (RESID) {
                    float2 rv = *(const float2*)&res[oi];
                    v0 += rv.x; v1 += rv.y;
                }
                float2 ov; ov.x = v0; ov.y = v1;
                *(float2*)&out[oi] = ov;
            }
        }
    }
}

// ---------------------------------------------------------------------------
// KPN aggregation. Radial interpolation tables are computed at COMPILE TIME
// so all channel indices are immediates -> core channels live in registers.
// ---------------------------------------------------------------------------
#define FST 33   // frame tile smem stride
#define FTH 30   // frame tile extent: 16 + 2*7

struct TEnt { int lo, hi, doff; bool inR; float a, b; };

__host__ __device__ constexpr double csqrt_(double x) {
    double g = x > 1.0 ? x : 1.0;
    for (int i = 0; i < 100; ++i) g = 0.5 * (g + x / g);
    return g;
}

__host__ __device__ constexpr TEnt tentry(int w, int p) {
    const int K = 2 * w - 1;
    const int r = w - 1;
    const int coff = w * (w - 1) / 2 - 1;   // 0,2,5,9,14,20,27
    const int i = p / K, j = p % K;
    TEnt e{};
    e.doff = (i - r) * FST + (j - r);
    const int s2 = (i - r) * (i - r) + (j - r) * (j - r);
    int q = 0;
    while ((q + 1) * (q + 1) <= s2) ++q;
    if (q * q == s2) {
        if (q > r) { e.inR = false; e.lo = coff; e.hi = coff; e.a = 0.f; e.b = 0.f; }
        else       { e.inR = true;  e.lo = coff + q; e.hi = coff + q; e.a = 1.f; e.b = 0.f; }
    } else {
        if (q >= r) { e.inR = false; e.lo = coff; e.hi = coff; e.a = 0.f; e.b = 0.f; }
        else {
            double d = csqrt_((double)s2);
            e.inR = true;
            e.lo = coff + q;
            e.hi = coff + q + 1;
            e.a = (float)((double)(q + 1) - d);
            e.b = (float)(d - (double)q);
        }
    }
    return e;
}

// Divide-and-conquer tap expansion: recursion depth O(log2 N).
template<int W, int Lo, int N>
struct KLoop {
    static __device__ __forceinline__ void run(const float (&c)[COUTF],
                                               const float* __restrict__ sF,
                                               int center, float& den, float& num) {
        KLoop<W, Lo, N / 2>::run(c, sF, center, den, num);
        KLoop<W, Lo + N / 2, N - N / 2>::run(c, sF, center, den, num);
    }
};

template<int W, int Lo>
struct KLoop<W, Lo, 1> {
    static __device__ __forceinline__ void run(const float (&c)[COUTF],
                                               const float* __restrict__ sF,
                                               int center, float& den, float& num) {
        constexpr TEnt e = tentry(W, Lo);
        float patch = sF[center + e.doff];
        if constexpr (e.inR) {
            float v = e.a * c[e.lo] + e.b * c[e.hi];
            float tt = __expf(v);
            den += tt;
            num += tt * patch;
        } else {
            den += 1.f;     // exp(0)
            num += patch;
        }
    }
};

template<int W, int Lo>
struct KLoop<W, Lo, 0> {
    static __device__ __forceinline__ void run(const float (&)[COUTF],
                                               const float* __restrict__,
                                               int, float&, float&) {}
};

template<int W>
__device__ __forceinline__ float section_run(const float (&c)[COUTF],
                                             const float* __restrict__ sF, int center) {
    constexpr int K = 2 * W - 1;
    float den = 0.f, num = 0.f;
    KLoop<W, 0, K * K>::run(c, sF, center, den, num);
    return num / den;
}

__global__ __launch_bounds__(256)
void kpn_kernel(const float* __restrict__ core, const float* __restrict__ data,
                float* __restrict__ out)
{
    __shared__ float sF[FTH * FST];
    const int t  = threadIdx.x;
    const int tx = t & 15, ty = t >> 4;
    const int bx = blockIdx.x, by = blockIdx.y, b = blockIdx.z;
    const int x  = bx * 16 + tx, y = by * 16 + ty;
    const int oy = by * 16 - 7,  ox = bx * 16 - 7;

    for (int idx = t; idx < FTH * FTH; idx += 256) {
        int fy = idx / FTH, fx = idx - fy * FTH;
        int gy = oy + fy,   gx = ox + fx;
        float v = 0.f;
        if (gy >= 0 && gy < HH && gx >= 0 && gx < WW)
            v = data[((size_t)b * HH + gy) * WW + gx];
        sF[fy * FST + fx] = v;
    }
    __syncthreads();

    float c[COUTF];
    #pragma unroll
    for (int ch = 0; ch < COUTF; ++ch)
        c[ch] = fabsf(core[(((size_t)b * COUTF + ch) * HH + y) * WW + x]);

    const int center = (ty + 7) * FST + (tx + 7);
    float pred = 0.f;
    pred += section_run<2>(c, sF, center);
    pred += section_run<3>(c, sF, center);
    pred += section_run<4>(c, sF, center);
    pred += section_run<5>(c, sF, center);
    pred += section_run<6>(c, sF, center);
    pred += section_run<7>(c, sF, center);
    pred += section_run<8>(c, sF, center);

    out[((size_t)b * HH + y) * WW + x] = pred;
}

// ---------------------------------------------------------------------------
// Launch
// ---------------------------------------------------------------------------
static inline int smem_bytes(int cin, int cb, int cout) {
    int copad = (cout + 3) / 4 * 4;
    return (cin * 9 * copad + cb * 6 * 68) * 4;
}

extern "C" void kernel_launch(void* const* d_in, const int* in_sizes, int n_in,
                              void* d_out, int out_size) {
    (void)in_sizes; (void)n_in; (void)out_size;
    const float* data_with_est = (const float*)d_in[0];
    const float* data    = (const float*)d_in[1];
    const float* w_first = (const float*)d_in[2];
    const float* b_first = (const float*)d_in[3];
    const float* w1a = (const float*)d_in[4];
    const float* b1a = (const float*)d_in[5];
    const float* w1b = (const float*)d_in[6];
    const float* b1b = (const float*)d_in[7];
    const float* w2a = (const float*)d_in[8];
    const float* b2a = (const float*)d_in[9];
    const float* w2b = (const float*)d_in[10];
    const float* b2b = (const float*)d_in[11];
    const float* w3a = (const float*)d_in[12];
    const float* b3a = (const float*)d_in[13];
    const float* w3b = (const float*)d_in[14];
    const float* b3b = (const float*)d_in[15];
    const float* w_out = (const float*)d_in[16];
    const float* b_out = (const float*)d_in[17];
    float* out = (float*)d_out;

    float *A = nullptr, *Bb = nullptr, *core = nullptr;
    cudaGetSymbolAddress((void**)&A, g_bufA);
    cudaGetSymbolAddress((void**)&Bb, g_bufB);
    cudaGetSymbolAddress((void**)&core, g_core);

    const int smFirst = smem_bytes(2, 2, NFC);
    const int smMain  = smem_bytes(NFC, 8, NFC);
    const int smOut   = smem_bytes(NFC, 8, COUTF);

    static bool attrSet = false;
    if (!attrSet) {
        cudaFuncSetAttribute(conv3x3<2, 2, NFC, false, false>,
                             cudaFuncAttributeMaxDynamicSharedMemorySize, smFirst);
        cudaFuncSetAttribute(conv3x3<NFC, 8, NFC, true, false>,
                             cudaFuncAttributeMaxDynamicSharedMemorySize, smMain);
        cudaFuncSetAttribute(conv3x3<NFC, 8, NFC, false, true>,
                             cudaFuncAttributeMaxDynamicSharedMemorySize, smMain);
        cudaFuncSetAttribute(conv3x3<NFC, 8, COUTF, false, false>,
                             cudaFuncAttributeMaxDynamicSharedMemorySize, smOut);
        attrSet = true;
    }

    dim3 cgrid(WW / 64, HH / 4, BB), cblk(512);

    // first conv: 2 -> 64, no relu
    conv3x3<2, 2, NFC, false, false><<<cgrid, cblk, smFirst>>>(data_with_est, w_first, b_first, nullptr, A);
    // resblock 1
    conv3x3<NFC, 8, NFC, true,  false><<<cgrid, cblk, smMain>>>(A,  w1a, b1a, nullptr, Bb);
    conv3x3<NFC, 8, NFC, false, true ><<<cgrid, cblk, smMain>>>(Bb, w1b, b1b, A, A);
    // resblock 2
    conv3x3<NFC, 8, NFC, true,  false><<<cgrid, cblk, smMain>>>(A,  w2a, b2a, nullptr, Bb);
    conv3x3<NFC, 8, NFC, false, true ><<<cgrid, cblk, smMain>>>(Bb, w2b, b2b, A, A);
    // resblock 3
    conv3x3<NFC, 8, NFC, true,  false><<<cgrid, cblk, smMain>>>(A,  w3a, b3a, nullptr, Bb);
    conv3x3<NFC, 8, NFC, false, true ><<<cgrid, cblk, smMain>>>(Bb, w3b, b3b, A, A);
    // output conv: 64 -> 35
    conv3x3<NFC, 8, COUTF, false, false><<<cgrid, cblk, smOut>>>(A, w_out, b_out, nullptr, core);

    // KPN aggregation
    kpn_kernel<<<dim3(WW / 16, HH / 16, BB), 256>>>(core, data, out);
}

// round 8
// speedup vs baseline: 4.7528x; 3.0540x over previous
#include <cuda_runtime.h>
#include <cstdint>
#include <cstddef>

#define HH 384
#define WW 384
#define BB 2
#define NFC 64
#define COUTF 35

__device__ float g_bufA[(size_t)BB * NFC * HH * WW];
__device__ float g_bufB[(size_t)BB * NFC * HH * WW];
__device__ float g_core[(size_t)BB * COUTF * HH * WW];

__device__ __forceinline__ uint32_t rna_tf32(float f) {
    uint32_t u; asm("cvt.rna.tf32.f32 %0, %1;" : "=r"(u) : "f"(f)); return u;
}

__device__ __forceinline__ void mma_tf32(float* d, const uint32_t* a, const uint32_t* b) {
    asm volatile("mma.sync.aligned.m16n8k8.row.col.f32.tf32.tf32.f32 "
                 "{%0,%1,%2,%3}, {%4,%5,%6,%7}, {%8,%9}, {%0,%1,%2,%3};"
                 : "+f"(d[0]), "+f"(d[1]), "+f"(d[2]), "+f"(d[3])
                 : "r"(a[0]), "r"(a[1]), "r"(a[2]), "r"(a[3]),
                   "r"(b[0]), "r"(b[1]));
}

// ---------------------------------------------------------------------------
// 3x3 conv as implicit GEMM on tf32 mma.sync.
// D[128px, 64co] = sum over taps/ci of X_shifted * W.
// Block 256 thr = 8 warps; tile 32 cols x 4 rows x 64 co.
// Warp (wm, wn): image row y0+wm, co range [32*wn, 32*wn+32).
// K-step = one tap x 8 input channels (k8). A frags read the shifted input
// tile directly (no im2col buffer). All smem conflict-free (checked).
// ---------------------------------------------------------------------------
template<int CIN, int COUT, bool RELU, bool RESID>
__global__ __launch_bounds__(256)
void conv_mma(const float* __restrict__ in, const float* __restrict__ wgt,
              const float* __restrict__ bias, const float* __restrict__ res,
              float* __restrict__ out)
{
    constexpr int CHUNKS = (CIN + 7) / 8;
    __shared__ uint32_t sX[8 * 6 * 36];     // [ci][row 0..5][col 0..35], tf32
    __shared__ uint32_t sW[9 * 64 * 12];    // [tap][co][ci pad 12], tf32

    const int t = threadIdx.x, lane = t & 31, wid = t >> 5;
    const int wm = wid & 3, wn = wid >> 2;
    const int x0 = blockIdx.x * 32, y0 = blockIdx.y * 4, b = blockIdx.z;
    const int gid = lane >> 2, tid4 = lane & 3;

    float acc[2][4][4];
    #pragma unroll
    for (int mt = 0; mt < 2; ++mt)
        #pragma unroll
        for (int nt = 0; nt < 4; ++nt)
            #pragma unroll
            for (int k = 0; k < 4; ++k) acc[mt][nt][k] = 0.f;

    for (int c = 0; c < CHUNKS; ++c) {
        __syncthreads();
        // --- stage input tile: 8 ch x 6 rows x 36 cols (34 used), zero-padded
        for (int idx = t; idx < 8 * 6 * 36; idx += 256) {
            int ci = idx / 216, rm = idx - ci * 216, r = rm / 36, s = rm - r * 36;
            int ch = c * 8 + ci;
            int gy = y0 - 1 + r, gx = x0 - 1 + s;
            float v = 0.f;
            if (ch < CIN && s < 34 && gy >= 0 && gy < HH && gx >= 0 && gx < WW)
                v = in[(((size_t)b * CIN + ch) * HH + gy) * WW + gx];
            sX[idx] = rna_tf32(v);
        }
        // --- stage weights: [tap][co][ci] for this chunk, zero-padded
        for (int idx = t; idx < 9 * 64 * 8; idx += 256) {
            int tap = idx >> 9, rm = idx & 511, co = rm >> 3, ci = rm & 7;
            int ch = c * 8 + ci;
            float w = 0.f;
            if (co < COUT && ch < CIN)
                w = wgt[((size_t)co * CIN + ch) * 9 + tap];
            sW[(tap * 64 + co) * 12 + ci] = rna_tf32(w);
        }
        __syncthreads();

        #pragma unroll
        for (int tap = 0; tap < 9; ++tap) {
            const int dy = tap / 3, dx = tap - dy * 3;
            uint32_t bf[4][2];
            #pragma unroll
            for (int nt = 0; nt < 4; ++nt) {
                int co = wn * 32 + nt * 8 + gid;
                const uint32_t* wp = &sW[(tap * 64 + co) * 12 + tid4];
                bf[nt][0] = wp[0];
                bf[nt][1] = wp[4];
            }
            #pragma unroll
            for (int mt = 0; mt < 2; ++mt) {
                uint32_t af[4];
                int base = tid4 * 216 + (wm + dy) * 36 + mt * 16 + gid + dx;
                af[0] = sX[base];
                af[1] = sX[base + 8];
                af[2] = sX[base + 4 * 216];
                af[3] = sX[base + 4 * 216 + 8];
                #pragma unroll
                for (int nt = 0; nt < 4; ++nt)
                    mma_tf32(acc[mt][nt], af, bf[nt]);
            }
        }
    }

    // --- epilogue: bias / relu / residual, guarded stores ---
    const int y = y0 + wm;
    #pragma unroll
    for (int nt = 0; nt < 4; ++nt) {
        int co0 = wn * 32 + nt * 8 + 2 * tid4;
        int co1 = co0 + 1;
        float bv0 = (co0 < COUT) ? bias[co0] : 0.f;
        float bv1 = (co1 < COUT) ? bias[co1] : 0.f;
        #pragma unroll
        for (int mt = 0; mt < 2; ++mt) {
            int x = x0 + mt * 16 + gid;
            if (co0 < COUT) {
                size_t o = (((size_t)b * COUT + co0) * HH + y) * WW + x;
                float v = acc[mt][nt][0] + bv0;
                if (RELU) v = fmaxf(v, 0.f);
                if (RESID) v += res[o];
                out[o] = v;
                float v2 = acc[mt][nt][2] + bv0;
                if (RELU) v2 = fmaxf(v2, 0.f);
                if (RESID) v2 += res[o + 8];
                out[o + 8] = v2;
            }
            if (co1 < COUT) {
                size_t o = (((size_t)b * COUT + co1) * HH + y) * WW + x;
                float v = acc[mt][nt][1] + bv1;
                if (RELU) v = fmaxf(v, 0.f);
                if (RESID) v += res[o];
                out[o] = v;
                float v2 = acc[mt][nt][3] + bv1;
                if (RELU) v2 = fmaxf(v2, 0.f);
                if (RESID) v2 += res[o + 8];
                out[o + 8] = v2;
            }
        }
    }
}

// ---------------- KPN aggregation (compile-time radial tables) ----------------
#define FST 33
#define FTH 30

struct TEnt { int lo, hi, doff; bool inR; float a, b; };

__host__ __device__ constexpr double csqrt_(double x) {
    double g = x > 1.0 ? x : 1.0;
    for (int i = 0; i < 100; ++i) g = 0.5 * (g + x / g);
    return g;
}
__host__ __device__ constexpr TEnt tentry(int w, int p) {
    const int K = 2 * w - 1, r = w - 1, coff = w * (w - 1) / 2 - 1;
    const int i = p / K, j = p % K;
    TEnt e{};
    e.doff = (i - r) * FST + (j - r);
    const int s2 = (i - r) * (i - r) + (j - r) * (j - r);
    int q = 0;
    while ((q + 1) * (q + 1) <= s2) ++q;
    if (q * q == s2) {
        if (q > r) { e.inR = false; e.lo = coff; e.hi = coff; e.a = 0.f; e.b = 0.f; }
        else       { e.inR = true;  e.lo = coff + q; e.hi = coff + q; e.a = 1.f; e.b = 0.f; }
    } else {
        if (q >= r) { e.inR = false; e.lo = coff; e.hi = coff; e.a = 0.f; e.b = 0.f; }
        else {
            double d = csqrt_((double)s2);
            e.inR = true; e.lo = coff + q; e.hi = coff + q + 1;
            e.a = (float)((double)(q + 1) - d);
            e.b = (float)(d - (double)q);
        }
    }
    return e;
}

template<int W, int Lo, int N>
struct KLoop {
    static __device__ __forceinline__ void run(const float (&c)[COUTF], const float* __restrict__ sF,
                                               int ctr, float& den, float& num) {
        KLoop<W, Lo, N / 2>::run(c, sF, ctr, den, num);
        KLoop<W, Lo + N / 2, N - N / 2>::run(c, sF, ctr, den, num);
    }
};
template<int W, int Lo>
struct KLoop<W, Lo, 1> {
    static __device__ __forceinline__ void run(const float (&c)[COUTF], const float* __restrict__ sF,
                                               int ctr, float& den, float& num) {
        constexpr TEnt e = tentry(W, Lo);
        float patch = sF[ctr + e.doff];
        if constexpr (e.inR) {
            float v = e.a * c[e.lo] + e.b * c[e.hi];
            float tt = __expf(v);
            den += tt; num += tt * patch;
        } else { den += 1.f; num += patch; }
    }
};
template<int W, int Lo>
struct KLoop<W, Lo, 0> {
    static __device__ __forceinline__ void run(const float (&)[COUTF], const float* __restrict__,
                                               int, float&, float&) {}
};

template<int W>
__device__ __forceinline__ float section_run(const float (&c)[COUTF], const float* __restrict__ sF, int ctr) {
    constexpr int K = 2 * W - 1;
    float den = 0.f, num = 0.f;
    KLoop<W, 0, K * K>::run(c, sF, ctr, den, num);
    return num / den;
}

__global__ __launch_bounds__(256)
void kpn_kernel(const float* __restrict__ core, const float* __restrict__ data,
                float* __restrict__ out)
{
    __shared__ float sF[FTH * FST];
    const int t = threadIdx.x, tx = t & 15, ty = t >> 4;
    const int bx = blockIdx.x, by = blockIdx.y, b = blockIdx.z;
    const int x = bx * 16 + tx, y = by * 16 + ty;
    const int oy = by * 16 - 7, ox = bx * 16 - 7;

    for (int idx = t; idx < FTH * FTH; idx += 256) {
        int fy = idx / FTH, fx = idx - fy * FTH;
        int gy = oy + fy, gx = ox + fx;
        float v = 0.f;
        if (gy >= 0 && gy < HH && gx >= 0 && gx < WW)
            v = data[((size_t)b * HH + gy) * WW + gx];
        sF[fy * FST + fx] = v;
    }
    __syncthreads();

    float c[COUTF];
    #pragma unroll
    for (int ch = 0; ch < COUTF; ++ch)
        c[ch] = fabsf(core[(((size_t)b * COUTF + ch) * HH + y) * WW + x]);

    const int ctr = (ty + 7) * FST + (tx + 7);
    float pred = 0.f;
    pred += section_run<2>(c, sF, ctr);
    pred += section_run<3>(c, sF, ctr);
    pred += section_run<4>(c, sF, ctr);
    pred += section_run<5>(c, sF, ctr);
    pred += section_run<6>(c, sF, ctr);
    pred += section_run<7>(c, sF, ctr);
    pred += section_run<8>(c, sF, ctr);

    out[((size_t)b * HH + y) * WW + x] = pred;
}

// ------------------------------- launch --------------------------------------
extern "C" void kernel_launch(void* const* d_in, const int* in_sizes, int n_in,
                              void* d_out, int out_size) {
    (void)in_sizes; (void)n_in; (void)out_size;
    const float* data_with_est = (const float*)d_in[0];
    const float* data  = (const float*)d_in[1];
    const float* w_first = (const float*)d_in[2];
    const float* b_first = (const float*)d_in[3];
    const float* w1a = (const float*)d_in[4];
    const float* b1a = (const float*)d_in[5];
    const float* w1b = (const float*)d_in[6];
    const float* b1b = (const float*)d_in[7];
    const float* w2a = (const float*)d_in[8];
    const float* b2a = (const float*)d_in[9];
    const float* w2b = (const float*)d_in[10];
    const float* b2b = (const float*)d_in[11];
    const float* w3a = (const float*)d_in[12];
    const float* b3a = (const float*)d_in[13];
    const float* w3b = (const float*)d_in[14];
    const float* b3b = (const float*)d_in[15];
    const float* w_out = (const float*)d_in[16];
    const float* b_out = (const float*)d_in[17];
    float* out = (float*)d_out;

    float *A = nullptr, *Bb = nullptr, *core = nullptr;
    cudaGetSymbolAddress((void**)&A, g_bufA);
    cudaGetSymbolAddress((void**)&Bb, g_bufB);
    cudaGetSymbolAddress((void**)&core, g_core);

    dim3 grid(WW / 32, HH / 4, BB), blk(256);

    conv_mma<2, NFC, false, false><<<grid, blk>>>(data_with_est, w_first, b_first, nullptr, A);
    conv_mma<NFC, NFC, true,  false><<<grid, blk>>>(A,  w1a, b1a, nullptr, Bb);
    conv_mma<NFC, NFC, false, true ><<<grid, blk>>>(Bb, w1b, b1b, A, A);
    conv_mma<NFC, NFC, true,  false><<<grid, blk>>>(A,  w2a, b2a, nullptr, Bb);
    conv_mma<NFC, NFC, false, true ><<<grid, blk>>>(Bb, w2b, b2b, A, A);
    conv_mma<NFC, NFC, true,  false><<<grid, blk>>>(A,  w3a, b3a, nullptr, Bb);
    conv_mma<NFC, NFC, false, true ><<<grid, blk>>>(Bb, w3b, b3b, A, A);
    conv_mma<NFC, COUTF, false, false><<<grid, blk>>>(A, w_out, b_out, nullptr, core);

    kpn_kernel<<<dim3(WW / 16, HH / 16, BB), 256>>>(core, data, out);
}

// round 9
// speedup vs baseline: 5.0739x; 1.0676x over previous
#include <cuda_runtime.h>
#include <cstdint>
#include <cstddef>

#define HH 384
#define WW 384
#define BB 2
#define NFC 64
#define COUTF 35

__device__ float g_bufA[(size_t)BB * NFC * HH * WW];
__device__ float g_bufB[(size_t)BB * NFC * HH * WW];
__device__ float g_core[(size_t)BB * COUTF * HH * WW];

__device__ __forceinline__ uint32_t rna_tf32(float f) {
    uint32_t u; asm("cvt.rna.tf32.f32 %0, %1;" : "=r"(u) : "f"(f)); return u;
}

__device__ __forceinline__ void mma_tf32(float* d, uint32_t a0, uint32_t a1,
                                         uint32_t a2, uint32_t a3,
                                         uint32_t b0, uint32_t b1) {
    asm volatile("mma.sync.aligned.m16n8k8.row.col.f32.tf32.tf32.f32 "
                 "{%0,%1,%2,%3}, {%4,%5,%6,%7}, {%8,%9}, {%0,%1,%2,%3};"
                 : "+f"(d[0]), "+f"(d[1]), "+f"(d[2]), "+f"(d[3])
                 : "r"(a0), "r"(a1), "r"(a2), "r"(a3), "r"(b0), "r"(b1));
}

// ---------------------------------------------------------------------------
// 3x3 conv as implicit GEMM on tf32 mma.sync, k-pair interleaved operands.
// Block 256 thr = 8 warps; tile 32 cols x 4 rows x 64 co.
// Warp (wm, wn): image row y0+wm, co range [32*wn, 32*wn+32).
// X: 4 pair-planes {ci, ci+4}, plane stride 228 uint2 (228 % 16 == 4 ->
//    conflict-free LDS.64). W: [tap][co][q]{ci=q, ci=q+4}, stride 4.
// All mainloop addresses = hoisted base + unroll-constant immediate.
// ---------------------------------------------------------------------------
template<int CIN, int COUT, bool RELU, bool RESID>
__global__ __launch_bounds__(256)
void conv_mma(const float* __restrict__ in, const float* __restrict__ wgt,
              const float* __restrict__ bias, const float* __restrict__ res,
              float* __restrict__ out)
{
    constexpr int CHUNKS = (CIN + 7) / 8;
    __shared__ uint2 sX2[4 * 228];        // pair-plane p: rows 6 x 36 cols used
    __shared__ uint2 sW2[9 * 64 * 4];     // [tap][co][q]

    const int t = threadIdx.x, lane = t & 31, wid = t >> 5;
    const int wm = wid & 3, wn = wid >> 2;
    const int x0 = blockIdx.x * 32, y0 = blockIdx.y * 4, b = blockIdx.z;
    const int gid = lane >> 2, tid4 = lane & 3;

    float acc[2][4][4];
    #pragma unroll
    for (int mt = 0; mt < 2; ++mt)
        #pragma unroll
        for (int nt = 0; nt < 4; ++nt)
            #pragma unroll
            for (int k = 0; k < 4; ++k) acc[mt][nt][k] = 0.f;

    const int abase = tid4 * 228 + wm * 36 + gid;      // uint2 units
    const int bbase = (wn * 32 + gid) * 4 + tid4;      // uint2 units

    for (int c = 0; c < CHUNKS; ++c) {
        __syncthreads();
        // --- stage X pair-planes: 4 x 6 x 36 (34 cols used), zero-padded ---
        for (int idx = t; idx < 4 * 216; idx += 256) {
            int p = idx / 216, rm = idx - p * 216, r = rm / 36, s = rm - r * 36;
            int ch0 = c * 8 + p, ch1 = ch0 + 4;
            int gy = y0 - 1 + r, gx = x0 - 1 + s;
            float v0 = 0.f, v1 = 0.f;
            bool inb = (s < 34 && gy >= 0 && gy < HH && gx >= 0 && gx < WW);
            if (inb && ch0 < CIN) v0 = in[(((size_t)b * CIN + ch0) * HH + gy) * WW + gx];
            if (inb && ch1 < CIN) v1 = in[(((size_t)b * CIN + ch1) * HH + gy) * WW + gx];
            uint2 u; u.x = rna_tf32(v0); u.y = rna_tf32(v1);
            sX2[p * 228 + r * 36 + s] = u;
        }
        // --- stage W: [tap][co][q] pairs, zero-padded ---
        for (int idx = t; idx < 9 * 64 * 4; idx += 256) {
            int tap = idx >> 8, rm = idx & 255, co = rm >> 2, q = rm & 3;
            int ch0 = c * 8 + q, ch1 = ch0 + 4;
            float w0 = 0.f, w1 = 0.f;
            if (co < COUT) {
                if (ch0 < CIN) w0 = wgt[((size_t)co * CIN + ch0) * 9 + tap];
                if (ch1 < CIN) w1 = wgt[((size_t)co * CIN + ch1) * 9 + tap];
            }
            uint2 u; u.x = rna_tf32(w0); u.y = rna_tf32(w1);
            sW2[idx] = u;
        }
        __syncthreads();

        #pragma unroll
        for (int tap = 0; tap < 9; ++tap) {
            const int dy = tap / 3, dx = tap - dy * 3;
            uint2 bf[4];
            #pragma unroll
            for (int nt = 0; nt < 4; ++nt)
                bf[nt] = sW2[tap * 256 + nt * 32 + bbase];
            #pragma unroll
            for (int mt = 0; mt < 2; ++mt) {
                uint2 a02 = sX2[abase + dy * 36 + dx + mt * 16];
                uint2 a13 = sX2[abase + dy * 36 + dx + mt * 16 + 8];
                #pragma unroll
                for (int nt = 0; nt < 4; ++nt)
                    mma_tf32(acc[mt][nt], a02.x, a13.x, a02.y, a13.y,
                             bf[nt].x, bf[nt].y);
            }
        }
    }

    // --- epilogue: bias / relu / residual, guarded stores ---
    const int y = y0 + wm;
    #pragma unroll
    for (int nt = 0; nt < 4; ++nt) {
        int co0 = wn * 32 + nt * 8 + 2 * tid4;
        int co1 = co0 + 1;
        float bv0 = (co0 < COUT) ? bias[co0] : 0.f;
        float bv1 = (co1 < COUT) ? bias[co1] : 0.f;
        #pragma unroll
        for (int mt = 0; mt < 2; ++mt) {
            int x = x0 + mt * 16 + gid;
            if (co0 < COUT) {
                size_t o = (((size_t)b * COUT + co0) * HH + y) * WW + x;
                float v = acc[mt][nt][0] + bv0;
                if (RELU) v = fmaxf(v, 0.f);
                if (RESID) v += res[o];
                out[o] = v;
                float v2 = acc[mt][nt][2] + bv0;
                if (RELU) v2 = fmaxf(v2, 0.f);
                if (RESID) v2 += res[o + 8];
                out[o + 8] = v2;
            }
            if (co1 < COUT) {
                size_t o = (((size_t)b * COUT + co1) * HH + y) * WW + x;
                float v = acc[mt][nt][1] + bv1;
                if (RELU) v = fmaxf(v, 0.f);
                if (RESID) v += res[o];
                out[o] = v;
                float v2 = acc[mt][nt][3] + bv1;
                if (RELU) v2 = fmaxf(v2, 0.f);
                if (RESID) v2 += res[o + 8];
                out[o + 8] = v2;
            }
        }
    }
}

// ---------------- KPN aggregation (compile-time radial tables) ----------------
#define FST 33
#define FTH 30

struct TEnt { int lo, hi, doff; bool inR; float a, b; };

__host__ __device__ constexpr double csqrt_(double x) {
    double g = x > 1.0 ? x : 1.0;
    for (int i = 0; i < 100; ++i) g = 0.5 * (g + x / g);
    return g;
}
__host__ __device__ constexpr TEnt tentry(int w, int p) {
    const int K = 2 * w - 1, r = w - 1, coff = w * (w - 1) / 2 - 1;
    const int i = p / K, j = p % K;
    TEnt e{};
    e.doff = (i - r) * FST + (j - r);
    const int s2 = (i - r) * (i - r) + (j - r) * (j - r);
    int q = 0;
    while ((q + 1) * (q + 1) <= s2) ++q;
    if (q * q == s2) {
        if (q > r) { e.inR = false; e.lo = coff; e.hi = coff; e.a = 0.f; e.b = 0.f; }
        else       { e.inR = true;  e.lo = coff + q; e.hi = coff + q; e.a = 1.f; e.b = 0.f; }
    } else {
        if (q >= r) { e.inR = false; e.lo = coff; e.hi = coff; e.a = 0.f; e.b = 0.f; }
        else {
            double d = csqrt_((double)s2);
            e.inR = true; e.lo = coff + q; e.hi = coff + q + 1;
            e.a = (float)((double)(q + 1) - d);
            e.b = (float)(d - (double)q);
        }
    }
    return e;
}

template<int W, int Lo, int N>
struct KLoop {
    static __device__ __forceinline__ void run(const float (&c)[COUTF], const float* __restrict__ sF,
                                               int ctr, float& den, float& num) {
        KLoop<W, Lo, N / 2>::run(c, sF, ctr, den, num);
        KLoop<W, Lo + N / 2, N - N / 2>::run(c, sF, ctr, den, num);
    }
};
template<int W, int Lo>
struct KLoop<W, Lo, 1> {
    static __device__ __forceinline__ void run(const float (&c)[COUTF], const float* __restrict__ sF,
                                               int ctr, float& den, float& num) {
        constexpr TEnt e = tentry(W, Lo);
        float patch = sF[ctr + e.doff];
        if constexpr (e.inR) {
            float v = e.a * c[e.lo] + e.b * c[e.hi];
            float tt = __expf(v);
            den += tt; num += tt * patch;
        } else { den += 1.f; num += patch; }
    }
};
template<int W, int Lo>
struct KLoop<W, Lo, 0> {
    static __device__ __forceinline__ void run(const float (&)[COUTF], const float* __restrict__,
                                               int, float&, float&) {}
};

template<int W>
__device__ __forceinline__ float section_run(const float (&c)[COUTF], const float* __restrict__ sF, int ctr) {
    constexpr int K = 2 * W - 1;
    float den = 0.f, num = 0.f;
    KLoop<W, 0, K * K>::run(c, sF, ctr, den, num);
    return num / den;
}

__global__ __launch_bounds__(256)
void kpn_kernel(const float* __restrict__ core, const float* __restrict__ data,
                float* __restrict__ out)
{
    __shared__ float sF[FTH * FST];
    const int t = threadIdx.x, tx = t & 15, ty = t >> 4;
    const int bx = blockIdx.x, by = blockIdx.y, b = blockIdx.z;
    const int x = bx * 16 + tx, y = by * 16 + ty;
    const int oy = by * 16 - 7, ox = bx * 16 - 7;

    for (int idx = t; idx < FTH * FTH; idx += 256) {
        int fy = idx / FTH, fx = idx - fy * FTH;
        int gy = oy + fy, gx = ox + fx;
        float v = 0.f;
        if (gy >= 0 && gy < HH && gx >= 0 && gx < WW)
            v = data[((size_t)b * HH + gy) * WW + gx];
        sF[fy * FST + fx] = v;
    }
    __syncthreads();

    float c[COUTF];
    #pragma unroll
    for (int ch = 0; ch < COUTF; ++ch)
        c[ch] = fabsf(core[(((size_t)b * COUTF + ch) * HH + y) * WW + x]);

    const int ctr = (ty + 7) * FST + (tx + 7);
    float pred = 0.f;
    pred += section_run<2>(c, sF, ctr);
    pred += section_run<3>(c, sF, ctr);
    pred += section_run<4>(c, sF, ctr);
    pred += section_run<5>(c, sF, ctr);
    pred += section_run<6>(c, sF, ctr);
    pred += section_run<7>(c, sF, ctr);
    pred += section_run<8>(c, sF, ctr);

    out[((size_t)b * HH + y) * WW + x] = pred;
}

// ------------------------------- launch --------------------------------------
extern "C" void kernel_launch(void* const* d_in, const int* in_sizes, int n_in,
                              void* d_out, int out_size) {
    (void)in_sizes; (void)n_in; (void)out_size;
    const float* data_with_est = (const float*)d_in[0];
    const float* data  = (const float*)d_in[1];
    const float* w_first = (const float*)d_in[2];
    const float* b_first = (const float*)d_in[3];
    const float* w1a = (const float*)d_in[4];
    const float* b1a = (const float*)d_in[5];
    const float* w1b = (const float*)d_in[6];
    const float* b1b = (const float*)d_in[7];
    const float* w2a = (const float*)d_in[8];
    const float* b2a = (const float*)d_in[9];
    const float* w2b = (const float*)d_in[10];
    const float* b2b = (const float*)d_in[11];
    const float* w3a = (const float*)d_in[12];
    const float* b3a = (const float*)d_in[13];
    const float* w3b = (const float*)d_in[14];
    const float* b3b = (const float*)d_in[15];
    const float* w_out = (const float*)d_in[16];
    const float* b_out = (const float*)d_in[17];
    float* out = (float*)d_out;

    float *A = nullptr, *Bb = nullptr, *core = nullptr;
    cudaGetSymbolAddress((void**)&A, g_bufA);
    cudaGetSymbolAddress((void**)&Bb, g_bufB);
    cudaGetSymbolAddress((void**)&core, g_core);

    dim3 grid(WW / 32, HH / 4, BB), blk(256);

    conv_mma<2, NFC, false, false><<<grid, blk>>>(data_with_est, w_first, b_first, nullptr, A);
    conv_mma<NFC, NFC, true,  false><<<grid, blk>>>(A,  w1a, b1a, nullptr, Bb);
    conv_mma<NFC, NFC, false, true ><<<grid, blk>>>(Bb, w1b, b1b, A, A);
    conv_mma<NFC, NFC, true,  false><<<grid, blk>>>(A,  w2a, b2a, nullptr, Bb);
    conv_mma<NFC, NFC, false, true ><<<grid, blk>>>(Bb, w2b, b2b, A, A);
    conv_mma<NFC, NFC, true,  false><<<grid, blk>>>(A,  w3a, b3a, nullptr, Bb);
    conv_mma<NFC, NFC, false, true ><<<grid, blk>>>(Bb, w3b, b3b, A, A);
    conv_mma<NFC, COUTF, false, false><<<grid, blk>>>(A, w_out, b_out, nullptr, core);

    kpn_kernel<<<dim3(WW / 16, HH / 16, BB), 256>>>(core, data, out);
}

// round 10
// speedup vs baseline: 5.4095x; 1.0661x over previous
#include <cuda_runtime.h>
#include <cstdint>
#include <cstddef>

#define HH 384
#define WW 384
#define BB 2
#define NFC 64
#define COUTF 35
#define HWSZ (HH * WW)

__device__ float g_bufA[(size_t)BB * NFC * HH * WW];
__device__ float g_bufB[(size_t)BB * NFC * HH * WW];
__device__ float g_core[(size_t)BB * COUTF * HH * WW];

__device__ __forceinline__ uint32_t rna_tf32(float f) {
    uint32_t u; asm("cvt.rna.tf32.f32 %0, %1;" : "=r"(u) : "f"(f)); return u;
}

__device__ __forceinline__ void mma_tf32(float* d, uint32_t a0, uint32_t a1,
                                         uint32_t a2, uint32_t a3,
                                         uint32_t b0, uint32_t b1) {
    asm volatile("mma.sync.aligned.m16n8k8.row.col.f32.tf32.tf32.f32 "
                 "{%0,%1,%2,%3}, {%4,%5,%6,%7}, {%8,%9}, {%0,%1,%2,%3};"
                 : "+f"(d[0]), "+f"(d[1]), "+f"(d[2]), "+f"(d[3])
                 : "r"(a0), "r"(a1), "r"(a2), "r"(a3), "r"(b0), "r"(b1));
}

// ---------------------------------------------------------------------------
// 3x3 conv as implicit GEMM, tf32 mma.sync, tile 64 px x 4 rows x 64 co.
// 8 warps: wm = row (0..3), wn = co half (0..1). Per warp mt=4 m16-tiles
// along x, nt=4 n8-tiles over co -> A reuse x4, B reuse x4 (1.5 wf/MMA).
// X smem: 4 pair-planes {ci, ci+4}, plane stride 420 uint2 (420%16==4 ->
// conflict-free LDS.64 per half-warp), row stride 68 (66 cols used).
// Staging: lane-contiguous (coalesced LDG + conflict-free STS), all offsets
// precomputed into registers before the chunk loop.
// ---------------------------------------------------------------------------
template<int CIN, int COUT, bool RELU, bool RESID>
__global__ __launch_bounds__(256, 2)
void conv_mma(const float* __restrict__ in, const float* __restrict__ wgt,
              const float* __restrict__ bias, const float* __restrict__ res,
              float* __restrict__ out)
{
    constexpr int CHUNKS = (CIN + 7) / 8;
    __shared__ uint2 sX2[4 * 420];
    __shared__ uint2 sW2[9 * 64 * 4];

    const int t = threadIdx.x, lane = t & 31, wid = t >> 5;
    const int wm = wid & 3, wn = wid >> 2;
    const int x0 = blockIdx.x * 64, y0 = blockIdx.y * 4, b = blockIdx.z;
    const int gid = lane >> 2, tid4 = lane & 3;

    // --- precompute X staging slots (7 x {smem off, global off}) ---
    int xsoff[7], xgoff[7];
    #pragma unroll
    for (int s7 = 0; s7 < 7; ++s7) {
        xsoff[s7] = -1; xgoff[s7] = -1;
        int ii = t + 256 * s7;
        if (ii < 1632) {                       // 24 plane-rows x 68 cols
            int pr = ii / 68, s = ii - pr * 68;
            int p = pr & 3, r = pr >> 2;
            int gy = y0 - 1 + r, gx = x0 - 1 + s;
            if (s < 66) {
                xsoff[s7] = p * 420 + r * 68 + s;
                bool chok = (CIN >= 8) || (p < CIN);
                if (gy >= 0 && gy < HH && gx >= 0 && gx < WW && chok)
                    xgoff[s7] = p * HWSZ + gy * WW + gx;
            }
        }
    }
    // --- precompute W staging slots (9 x global index) ---
    int wb[9];
    #pragma unroll
    for (int s9 = 0; s9 < 9; ++s9) {
        int i = t + 256 * s9;                  // 2304 = [tap][co][q] linear
        int tap = i >> 8, co = (i >> 2) & 63, q = i & 3;
        bool ok = (co < COUT) && ((CIN >= 8) || (q < CIN));
        wb[s9] = ok ? (co * CIN + q) * 9 + tap : -1;
    }

    float acc[4][4][4];
    #pragma unroll
    for (int mt = 0; mt < 4; ++mt)
        #pragma unroll
        for (int nt = 0; nt < 4; ++nt)
            #pragma unroll
            for (int k = 0; k < 4; ++k) acc[mt][nt][k] = 0.f;

    const int abase = tid4 * 420 + wm * 68 + gid;
    const int bbase = (wn * 32 + gid) * 4 + tid4;
    const float* inb = in + (size_t)b * CIN * HWSZ;

    for (int c = 0; c < CHUNKS; ++c) {
        __syncthreads();
        // X staging: coalesced LDG, conflict-free STS.64
        const float* inc = inb + (size_t)c * 8 * HWSZ;
        #pragma unroll
        for (int s7 = 0; s7 < 7; ++s7) {
            int so = xsoff[s7];
            if (so >= 0) {
                float v0 = 0.f, v1 = 0.f;
                int go = xgoff[s7];
                if (go >= 0) {
                    v0 = inc[go];
                    if (CIN >= 8) v1 = inc[go + 4 * HWSZ];
                }
                uint2 u; u.x = rna_tf32(v0); u.y = rna_tf32(v1);
                sX2[so] = u;
            }
        }
        // W staging
        #pragma unroll
        for (int s9 = 0; s9 < 9; ++s9) {
            float w0 = 0.f, w1 = 0.f;
            int wo = wb[s9];
            if (wo >= 0) {
                w0 = wgt[wo];
                if (CIN >= 8) w1 = wgt[wo + 36];
                wb[s9] = wo + 72;
            }
            uint2 u; u.x = rna_tf32(w0); u.y = rna_tf32(w1);
            sW2[t + 256 * s9] = u;
        }
        __syncthreads();

        #pragma unroll
        for (int tap = 0; tap < 9; ++tap) {
            const int dy = tap / 3, dx = tap - dy * 3;
            uint2 bf[4];
            #pragma unroll
            for (int nt = 0; nt < 4; ++nt)
                bf[nt] = sW2[tap * 256 + nt * 32 + bbase];
            #pragma unroll
            for (int mt = 0; mt < 4; ++mt) {
                uint2 a02 = sX2[abase + dy * 68 + dx + mt * 16];
                uint2 a13 = sX2[abase + dy * 68 + dx + mt * 16 + 8];
                #pragma unroll
                for (int nt = 0; nt < 4; ++nt)
                    mma_tf32(acc[mt][nt], a02.x, a13.x, a02.y, a13.y,
                             bf[nt].x, bf[nt].y);
            }
        }
    }

    // --- epilogue ---
    const int y = y0 + wm;
    #pragma unroll
    for (int nt = 0; nt < 4; ++nt) {
        int co0 = wn * 32 + nt * 8 + 2 * tid4;
        int co1 = co0 + 1;
        float bv0 = (co0 < COUT) ? bias[co0] : 0.f;
        float bv1 = (co1 < COUT) ? bias[co1] : 0.f;
        #pragma unroll
        for (int mt = 0; mt < 4; ++mt) {
            int x = x0 + mt * 16 + gid;
            if (co0 < COUT) {
                size_t o = (((size_t)b * COUT + co0) * HH + y) * WW + x;
                float v = acc[mt][nt][0] + bv0;
                if (RELU) v = fmaxf(v, 0.f);
                if (RESID) v += res[o];
                out[o] = v;
                float v2 = acc[mt][nt][2] + bv0;
                if (RELU) v2 = fmaxf(v2, 0.f);
                if (RESID) v2 += res[o + 8];
                out[o + 8] = v2;
            }
            if (co1 < COUT) {
                size_t o = (((size_t)b * COUT + co1) * HH + y) * WW + x;
                float v = acc[mt][nt][1] + bv1;
                if (RELU) v = fmaxf(v, 0.f);
                if (RESID) v += res[o];
                out[o] = v;
                float v2 = acc[mt][nt][3] + bv1;
                if (RELU) v2 = fmaxf(v2, 0.f);
                if (RESID) v2 += res[o + 8];
                out[o + 8] = v2;
            }
        }
    }
}

// ---------------- KPN aggregation (compile-time radial tables) ----------------
#define FST 33
#define FTH 30

struct TEnt { int lo, hi, doff; bool inR; float a, b; };

__host__ __device__ constexpr double csqrt_(double x) {
    double g = x > 1.0 ? x : 1.0;
    for (int i = 0; i < 100; ++i) g = 0.5 * (g + x / g);
    return g;
}
__host__ __device__ constexpr TEnt tentry(int w, int p) {
    const int K = 2 * w - 1, r = w - 1, coff = w * (w - 1) / 2 - 1;
    const int i = p / K, j = p % K;
    TEnt e{};
    e.doff = (i - r) * FST + (j - r);
    const int s2 = (i - r) * (i - r) + (j - r) * (j - r);
    int q = 0;
    while ((q + 1) * (q + 1) <= s2) ++q;
    if (q * q == s2) {
        if (q > r) { e.inR = false; e.lo = coff; e.hi = coff; e.a = 0.f; e.b = 0.f; }
        else       { e.inR = true;  e.lo = coff + q; e.hi = coff + q; e.a = 1.f; e.b = 0.f; }
    } else {
        if (q >= r) { e.inR = false; e.lo = coff; e.hi = coff; e.a = 0.f; e.b = 0.f; }
        else {
            double d = csqrt_((double)s2);
            e.inR = true; e.lo = coff + q; e.hi = coff + q + 1;
            e.a = (float)((double)(q + 1) - d);
            e.b = (float)(d - (double)q);
        }
    }
    return e;
}

template<int W, int Lo, int N>
struct KLoop {
    static __device__ __forceinline__ void run(const float (&c)[COUTF], const float* __restrict__ sF,
                                               int ctr, float& den, float& num) {
        KLoop<W, Lo, N / 2>::run(c, sF, ctr, den, num);
        KLoop<W, Lo + N / 2, N - N / 2>::run(c, sF, ctr, den, num);
    }
};
template<int W, int Lo>
struct KLoop<W, Lo, 1> {
    static __device__ __forceinline__ void run(const float (&c)[COUTF], const float* __restrict__ sF,
                                               int ctr, float& den, float& num) {
        constexpr TEnt e = tentry(W, Lo);
        float patch = sF[ctr + e.doff];
        if constexpr (e.inR) {
            float v = e.a * c[e.lo] + e.b * c[e.hi];
            float tt = __expf(v);
            den += tt; num += tt * patch;
        } else { den += 1.f; num += patch; }
    }
};
template<int W, int Lo>
struct KLoop<W, Lo, 0> {
    static __device__ __forceinline__ void run(const float (&)[COUTF], const float* __restrict__,
                                               int, float&, float&) {}
};

template<int W>
__device__ __forceinline__ float section_run(const float (&c)[COUTF], const float* __restrict__ sF, int ctr) {
    constexpr int K = 2 * W - 1;
    float den = 0.f, num = 0.f;
    KLoop<W, 0, K * K>::run(c, sF, ctr, den, num);
    return num / den;
}

__global__ __launch_bounds__(256)
void kpn_kernel(const float* __restrict__ core, const float* __restrict__ data,
                float* __restrict__ out)
{
    __shared__ float sF[FTH * FST];
    const int t = threadIdx.x, tx = t & 15, ty = t >> 4;
    const int bx = blockIdx.x, by = blockIdx.y, b = blockIdx.z;
    const int x = bx * 16 + tx, y = by * 16 + ty;
    const int oy = by * 16 - 7, ox = bx * 16 - 7;

    for (int idx = t; idx < FTH * FTH; idx += 256) {
        int fy = idx / FTH, fx = idx - fy * FTH;
        int gy = oy + fy, gx = ox + fx;
        float v = 0.f;
        if (gy >= 0 && gy < HH && gx >= 0 && gx < WW)
            v = data[((size_t)b * HH + gy) * WW + gx];
        sF[fy * FST + fx] = v;
    }
    __syncthreads();

    float c[COUTF];
    #pragma unroll
    for (int ch = 0; ch < COUTF; ++ch)
        c[ch] = fabsf(core[(((size_t)b * COUTF + ch) * HH + y) * WW + x]);

    const int ctr = (ty + 7) * FST + (tx + 7);
    float pred = 0.f;
    pred += section_run<2>(c, sF, ctr);
    pred += section_run<3>(c, sF, ctr);
    pred += section_run<4>(c, sF, ctr);
    pred += section_run<5>(c, sF, ctr);
    pred += section_run<6>(c, sF, ctr);
    pred += section_run<7>(c, sF, ctr);
    pred += section_run<8>(c, sF, ctr);

    out[((size_t)b * HH + y) * WW + x] = pred;
}

// ------------------------------- launch --------------------------------------
extern "C" void kernel_launch(void* const* d_in, const int* in_sizes, int n_in,
                              void* d_out, int out_size) {
    (void)in_sizes; (void)n_in; (void)out_size;
    const float* data_with_est = (const float*)d_in[0];
    const float* data  = (const float*)d_in[1];
    const float* w_first = (const float*)d_in[2];
    const float* b_first = (const float*)d_in[3];
    const float* w1a = (const float*)d_in[4];
    const float* b1a = (const float*)d_in[5];
    const float* w1b = (const float*)d_in[6];
    const float* b1b = (const float*)d_in[7];
    const float* w2a = (const float*)d_in[8];
    const float* b2a = (const float*)d_in[9];
    const float* w2b = (const float*)d_in[10];
    const float* b2b = (const float*)d_in[11];
    const float* w3a = (const float*)d_in[12];
    const float* b3a = (const float*)d_in[13];
    const float* w3b = (const float*)d_in[14];
    const float* b3b = (const float*)d_in[15];
    const float* w_out = (const float*)d_in[16];
    const float* b_out = (const float*)d_in[17];
    float* out = (float*)d_out;

    float *A = nullptr, *Bb = nullptr, *core = nullptr;
    cudaGetSymbolAddress((void**)&A, g_bufA);
    cudaGetSymbolAddress((void**)&Bb, g_bufB);
    cudaGetSymbolAddress((void**)&core, g_core);

    dim3 grid(WW / 64, HH / 4, BB), blk(256);

    conv_mma<2, NFC, false, false><<<grid, blk>>>(data_with_est, w_first, b_first, nullptr, A);
    conv_mma<NFC, NFC, true,  false><<<grid, blk>>>(A,  w1a, b1a, nullptr, Bb);
    conv_mma<NFC, NFC, false, true ><<<grid, blk>>>(Bb, w1b, b1b, A, A);
    conv_mma<NFC, NFC, true,  false><<<grid, blk>>>(A,  w2a, b2a, nullptr, Bb);
    conv_mma<NFC, NFC, false, true ><<<grid, blk>>>(Bb, w2b, b2b, A, A);
    conv_mma<NFC, NFC, true,  false><<<grid, blk>>>(A,  w3a, b3a, nullptr, Bb);
    conv_mma<NFC, NFC, false, true ><<<grid, blk>>>(Bb, w3b, b3b, A, A);
    conv_mma<NFC, COUTF, false, false><<<grid, blk>>>(A, w_out, b_out, nullptr, core);

    kpn_kernel<<<dim3(WW / 16, HH / 16, BB), 256>>>(core, data, out);
}

// round 11
// speedup vs baseline: 8.2577x; 1.5265x over previous
#include <cuda_runtime.h>
#include <cstdint>
#include <cstddef>

#define HH 384
#define WW 384
#define BB 2
#define NFC 64
#define COUTF 35
#define HWSZ (HH * WW)

__device__ float g_bufA[(size_t)BB * NFC * HH * WW];
__device__ float g_bufB[(size_t)BB * NFC * HH * WW];
__device__ float g_core[(size_t)BB * COUTF * HH * WW];
__device__ float g_xin[(size_t)BB * 2 * HWSZ];
__device__ uint2 g_wpack[131328];   // packed tf32 weights, all 8 layers

__device__ __forceinline__ uint32_t rna_tf32(float f) {
    uint32_t u; asm("cvt.rna.tf32.f32 %0, %1;" : "=r"(u) : "f"(f)); return u;
}
__device__ __forceinline__ uint32_t smem_u32(const void* p) {
    uint32_t a;
    asm("{ .reg .u64 t; cvta.to.shared.u64 t, %1; cvt.u32.u64 %0, t; }" : "=r"(a) : "l"(p));
    return a;
}
__device__ __forceinline__ void cpa4(uint32_t sa, const void* g, int n) {
    asm volatile("cp.async.ca.shared.global [%0], [%1], 4, %2;" :: "r"(sa), "l"(g), "r"(n));
}
__device__ __forceinline__ void cpa16(uint32_t sa, const void* g) {
    asm volatile("cp.async.cg.shared.global [%0], [%1], 16;" :: "r"(sa), "l"(g));
}
#define CPA_COMMIT() asm volatile("cp.async.commit_group;" ::: "memory")
#define CPA_WAIT0()  asm volatile("cp.async.wait_group 0;" ::: "memory")

__device__ __forceinline__ void mma_tf32(float* d, uint32_t a0, uint32_t a1,
                                         uint32_t a2, uint32_t a3,
                                         uint32_t b0, uint32_t b1) {
    asm volatile("mma.sync.aligned.m16n8k8.row.col.f32.tf32.tf32.f32 "
                 "{%0,%1,%2,%3}, {%4,%5,%6,%7}, {%8,%9}, {%0,%1,%2,%3};"
                 : "+f"(d[0]), "+f"(d[1]), "+f"(d[2]), "+f"(d[3])
                 : "r"(a0), "r"(a1), "r"(a2), "r"(a3), "r"(b0), "r"(b1));
}

// ---------------- prepass: pack + round weights ----------------
template<int CIN, int COUT>
__global__ void pack_w(const float* __restrict__ wgt, uint2* __restrict__ dst) {
    constexpr int CH = (CIN + 7) / 8;
    int idx = blockIdx.x * 256 + threadIdx.x;
    if (idx >= CH * 2304) return;
    int c = idx / 2304, slot = idx - c * 2304;
    int tap = slot >> 8, co = (slot >> 2) & 63, q = slot & 3;
    int ci0 = c * 8 + q, ci1 = ci0 + 4;
    uint2 u; u.x = 0; u.y = 0;
    if (co < COUT && ci0 < CIN) u.x = rna_tf32(wgt[((size_t)co * CIN + ci0) * 9 + tap]);
    if (co < COUT && ci1 < CIN) u.y = rna_tf32(wgt[((size_t)co * CIN + ci1) * 9 + tap]);
    dst[idx] = u;
}
__global__ void round_in(const float* __restrict__ src, float* __restrict__ dst, int n) {
    int i = blockIdx.x * 256 + threadIdx.x;
    if (i < n) dst[i] = __uint_as_float(rna_tf32(src[i]));
}

// ---------------------------------------------------------------------------
// 3x3 conv as implicit GEMM, tf32 mma.sync, cp.async double-buffered.
// Tile 64 px x 4 rows x 64 co; 8 warps; warp tile mt=4 x nt=4.
// smem (dynamic 63744B): X[2][4 planes x 420 uint2], W[2][2304 uint2].
// ---------------------------------------------------------------------------
template<int CIN, int COUT, bool RELU, bool RESID, bool ROUND>
__global__ __launch_bounds__(256, 2)
void conv_mma(const float* __restrict__ in, const uint4* __restrict__ wsrc,
              const float* __restrict__ bias, const float* __restrict__ res,
              float* __restrict__ out)
{
    constexpr int CHUNKS = (CIN + 7) / 8;
    extern __shared__ char smem[];
    const uint32_t sbase = smem_u32(smem);

    const int t = threadIdx.x, lane = t & 31, wid = t >> 5;
    const int wm = wid & 3, wn = wid >> 2;
    const int x0 = blockIdx.x * 64, y0 = blockIdx.y * 4, b = blockIdx.z;
    const int gid = lane >> 2, tid4 = lane & 3;

    // ---- X staging slots: 7 per thread; flags bit0=ch0 valid, bit1=ch1 valid
    int xsoff[7], xgoff[7];
    uint32_t xfl = 0;
    #pragma unroll
    for (int s7 = 0; s7 < 7; ++s7) {
        xsoff[s7] = -1; xgoff[s7] = 0;
        int ii = t + 256 * s7;
        if (ii < 1632) {
            int pr = ii / 68, s = ii - pr * 68;
            int p = pr & 3, r = pr >> 2;
            int gy = y0 - 1 + r, gx = x0 + s - 1;
            if (s < 66) {
                xsoff[s7] = p * 420 + r * 68 + s;
                bool inb = (gy >= 0 && gy < HH && gx >= 0 && gx < WW);
                if (inb && p < CIN) { xgoff[s7] = p * HWSZ + gy * WW + gx; xfl |= 1u << (2 * s7); }
                if (inb && p + 4 < CIN) xfl |= 2u << (2 * s7);
            }
        }
    }

    float acc[4][4][4];
    #pragma unroll
    for (int mt = 0; mt < 4; ++mt)
        #pragma unroll
        for (int nt = 0; nt < 4; ++nt)
            #pragma unroll
            for (int k = 0; k < 4; ++k) acc[mt][nt][k] = 0.f;

    const int abase = tid4 * 420 + wm * 68 + gid;
    const int bbase = (wn * 32 + gid) * 4 + tid4;
    const float* inb_p = in + (size_t)b * CIN * HWSZ;

    auto prefetch = [&](int c) {
        const uint32_t xb = sbase + (c & 1) * 13440;
        const float* inc = inb_p + (size_t)c * 8 * HWSZ;
        #pragma unroll
        for (int s7 = 0; s7 < 7; ++s7) {
            int so = xsoff[s7];
            if (so >= 0) {
                uint32_t sa = xb + so * 8;
                int f = (int)(xfl >> (2 * s7));
                int n0 = (f & 1) ? 4 : 0;
                int n1 = (f & 2) ? 4 : 0;
                const float* g = inc + xgoff[s7];
                cpa4(sa, g, n0);
                cpa4(sa + 4, n1 ? (g + 4 * HWSZ) : inc, n1);
            }
        }
        const uint32_t wbse = sbase + 26880 + (c & 1) * 18432;
        const uint4* ws = wsrc + (size_t)c * 1152;
        #pragma unroll
        for (int s5 = 0; s5 < 5; ++s5) {
            int i = t + 256 * s5;
            if (i < 1152) cpa16(wbse + i * 16, ws + i);
        }
        CPA_COMMIT();
    };

    prefetch(0);
    for (int c = 0; c < CHUNKS; ++c) {
        CPA_WAIT0();
        __syncthreads();
        if (c + 1 < CHUNKS) prefetch(c + 1);
        const uint2* sX2 = (const uint2*)(smem + (c & 1) * 13440);
        const uint2* sW2 = (const uint2*)(smem + 26880 + (c & 1) * 18432);

        #pragma unroll
        for (int tap = 0; tap < 9; ++tap) {
            const int dy = tap / 3, dx = tap - dy * 3;
            uint2 bf[4];
            #pragma unroll
            for (int nt = 0; nt < 4; ++nt)
                bf[nt] = sW2[tap * 256 + nt * 32 + bbase];
            #pragma unroll
            for (int mt = 0; mt < 4; ++mt) {
                uint2 a02 = sX2[abase + dy * 68 + dx + mt * 16];
                uint2 a13 = sX2[abase + dy * 68 + dx + mt * 16 + 8];
                #pragma unroll
                for (int nt = 0; nt < 4; ++nt)
                    mma_tf32(acc[mt][nt], a02.x, a13.x, a02.y, a13.y,
                             bf[nt].x, bf[nt].y);
            }
        }
    }

    // ---- epilogue ----
    const int y = y0 + wm;
    #pragma unroll
    for (int nt = 0; nt < 4; ++nt) {
        int co0 = wn * 32 + nt * 8 + 2 * tid4;
        int co1 = co0 + 1;
        float bv0 = (co0 < COUT) ? bias[co0] : 0.f;
        float bv1 = (co1 < COUT) ? bias[co1] : 0.f;
        #pragma unroll
        for (int mt = 0; mt < 4; ++mt) {
            int x = x0 + mt * 16 + gid;
            #pragma unroll
            for (int half = 0; half < 2; ++half) {
                int co = half ? co1 : co0;
                float bv = half ? bv1 : bv0;
                if (co < COUT) {
                    size_t o = (((size_t)b * COUT + co) * HH + y) * WW + x;
                    float v = acc[mt][nt][half] + bv;
                    if (RELU) v = fmaxf(v, 0.f);
                    if (RESID) v += res[o];
                    out[o] = ROUND ? __uint_as_float(rna_tf32(v)) : v;
                    float v2 = acc[mt][nt][2 + half] + bv;
                    if (RELU) v2 = fmaxf(v2, 0.f);
                    if (RESID) v2 += res[o + 8];
                    out[o + 8] = ROUND ? __uint_as_float(rna_tf32(v2)) : v2;
                }
            }
        }
    }
}

// ---------------- KPN aggregation (compile-time radial tables) ----------------
#define FST 33
#define FTH 30

struct TEnt { int lo, hi, doff; bool inR; float a, b; };

__host__ __device__ constexpr double csqrt_(double x) {
    double g = x > 1.0 ? x : 1.0;
    for (int i = 0; i < 100; ++i) g = 0.5 * (g + x / g);
    return g;
}
__host__ __device__ constexpr TEnt tentry(int w, int p) {
    const int K = 2 * w - 1, r = w - 1, coff = w * (w - 1) / 2 - 1;
    const int i = p / K, j = p % K;
    TEnt e{};
    e.doff = (i - r) * FST + (j - r);
    const int s2 = (i - r) * (i - r) + (j - r) * (j - r);
    int q = 0;
    while ((q + 1) * (q + 1) <= s2) ++q;
    if (q * q == s2) {
        if (q > r) { e.inR = false; e.lo = coff; e.hi = coff; e.a = 0.f; e.b = 0.f; }
        else       { e.inR = true;  e.lo = coff + q; e.hi = coff + q; e.a = 1.f; e.b = 0.f; }
    } else {
        if (q >= r) { e.inR = false; e.lo = coff; e.hi = coff; e.a = 0.f; e.b = 0.f; }
        else {
            double d = csqrt_((double)s2);
            e.inR = true; e.lo = coff + q; e.hi = coff + q + 1;
            e.a = (float)((double)(q + 1) - d);
            e.b = (float)(d - (double)q);
        }
    }
    return e;
}

template<int W, int Lo, int N>
struct KLoop {
    static __device__ __forceinline__ void run(const float (&c)[COUTF], const float* __restrict__ sF,
                                               int ctr, float& den, float& num) {
        KLoop<W, Lo, N / 2>::run(c, sF, ctr, den, num);
        KLoop<W, Lo + N / 2, N - N / 2>::run(c, sF, ctr, den, num);
    }
};
template<int W, int Lo>
struct KLoop<W, Lo, 1> {
    static __device__ __forceinline__ void run(const float (&c)[COUTF], const float* __restrict__ sF,
                                               int ctr, float& den, float& num) {
        constexpr TEnt e = tentry(W, Lo);
        float patch = sF[ctr + e.doff];
        if constexpr (e.inR) {
            float v = e.a * c[e.lo] + e.b * c[e.hi];
            float tt = __expf(v);
            den += tt; num += tt * patch;
        } else { den += 1.f; num += patch; }
    }
};
template<int W, int Lo>
struct KLoop<W, Lo, 0> {
    static __device__ __forceinline__ void run(const float (&)[COUTF], const float* __restrict__,
                                               int, float&, float&) {}
};

template<int W>
__device__ __forceinline__ float section_run(const float (&c)[COUTF], const float* __restrict__ sF, int ctr) {
    constexpr int K = 2 * W - 1;
    float den = 0.f, num = 0.f;
    KLoop<W, 0, K * K>::run(c, sF, ctr, den, num);
    return num / den;
}

__global__ __launch_bounds__(256)
void kpn_kernel(const float* __restrict__ core, const float* __restrict__ data,
                float* __restrict__ out)
{
    __shared__ float sF[FTH * FST];
    const int t = threadIdx.x, tx = t & 15, ty = t >> 4;
    const int bx = blockIdx.x, by = blockIdx.y, b = blockIdx.z;
    const int x = bx * 16 + tx, y = by * 16 + ty;
    const int oy = by * 16 - 7, ox = bx * 16 - 7;

    for (int idx = t; idx < FTH * FTH; idx += 256) {
        int fy = idx / FTH, fx = idx - fy * FTH;
        int gy = oy + fy, gx = ox + fx;
        float v = 0.f;
        if (gy >= 0 && gy < HH && gx >= 0 && gx < WW)
            v = data[((size_t)b * HH + gy) * WW + gx];
        sF[fy * FST + fx] = v;
    }
    __syncthreads();

    float c[COUTF];
    #pragma unroll
    for (int ch = 0; ch < COUTF; ++ch)
        c[ch] = fabsf(core[(((size_t)b * COUTF + ch) * HH + y) * WW + x]);

    const int ctr = (ty + 7) * FST + (tx + 7);
    float pred = 0.f;
    pred += section_run<2>(c, sF, ctr);
    pred += section_run<3>(c, sF, ctr);
    pred += section_run<4>(c, sF, ctr);
    pred += section_run<5>(c, sF, ctr);
    pred += section_run<6>(c, sF, ctr);
    pred += section_run<7>(c, sF, ctr);
    pred += section_run<8>(c, sF, ctr);

    out[((size_t)b * HH + y) * WW + x] = pred;
}

// ------------------------------- launch --------------------------------------
#define SMEMSZ 63744

extern "C" void kernel_launch(void* const* d_in, const int* in_sizes, int n_in,
                              void* d_out, int out_size) {
    (void)in_sizes; (void)n_in; (void)out_size;
    const float* data_with_est = (const float*)d_in[0];
    const float* data  = (const float*)d_in[1];
    const float* w_first = (const float*)d_in[2];
    const float* b_first = (const float*)d_in[3];
    const float* w1a = (const float*)d_in[4];
    const float* b1a = (const float*)d_in[5];
    const float* w1b = (const float*)d_in[6];
    const float* b1b = (const float*)d_in[7];
    const float* w2a = (const float*)d_in[8];
    const float* b2a = (const float*)d_in[9];
    const float* w2b = (const float*)d_in[10];
    const float* b2b = (const float*)d_in[11];
    const float* w3a = (const float*)d_in[12];
    const float* b3a = (const float*)d_in[13];
    const float* w3b = (const float*)d_in[14];
    const float* b3b = (const float*)d_in[15];
    const float* w_out = (const float*)d_in[16];
    const float* b_out = (const float*)d_in[17];
    float* out = (float*)d_out;

    float *A = nullptr, *Bb = nullptr, *core = nullptr, *xin = nullptr;
    uint2* wp = nullptr;
    cudaGetSymbolAddress((void**)&A, g_bufA);
    cudaGetSymbolAddress((void**)&Bb, g_bufB);
    cudaGetSymbolAddress((void**)&core, g_core);
    cudaGetSymbolAddress((void**)&xin, g_xin);
    cudaGetSymbolAddress((void**)&wp, g_wpack);

    // packed-weight layer offsets (uint2 units)
    const size_t off0 = 0, off1 = 2304, off2 = 20736, off3 = 39168,
                 off4 = 57600, off5 = 76032, off6 = 94464, off7 = 112896;

    cudaFuncSetAttribute(conv_mma<2, NFC, false, false, true>, cudaFuncAttributeMaxDynamicSharedMemorySize, SMEMSZ);
    cudaFuncSetAttribute(conv_mma<NFC, NFC, true, false, true>, cudaFuncAttributeMaxDynamicSharedMemorySize, SMEMSZ);
    cudaFuncSetAttribute(conv_mma<NFC, NFC, false, true, true>, cudaFuncAttributeMaxDynamicSharedMemorySize, SMEMSZ);
    cudaFuncSetAttribute(conv_mma<NFC, COUTF, false, false, false>, cudaFuncAttributeMaxDynamicSharedMemorySize, SMEMSZ);

    // prepasses
    round_in<<<(BB * 2 * HWSZ + 255) / 256, 256>>>(data_with_est, xin, BB * 2 * HWSZ);
    pack_w<2, NFC><<<(1 * 2304 + 255) / 256, 256>>>(w_first, wp + off0);
    pack_w<NFC, NFC><<<(8 * 2304 + 255) / 256, 256>>>(w1a, wp + off1);
    pack_w<NFC, NFC><<<(8 * 2304 + 255) / 256, 256>>>(w1b, wp + off2);
    pack_w<NFC, NFC><<<(8 * 2304 + 255) / 256, 256>>>(w2a, wp + off3);
    pack_w<NFC, NFC><<<(8 * 2304 + 255) / 256, 256>>>(w2b, wp + off4);
    pack_w<NFC, NFC><<<(8 * 2304 + 255) / 256, 256>>>(w3a, wp + off5);
    pack_w<NFC, NFC><<<(8 * 2304 + 255) / 256, 256>>>(w3b, wp + off6);
    pack_w<NFC, COUTF><<<(8 * 2304 + 255) / 256, 256>>>(w_out, wp + off7);

    dim3 grid(WW / 64, HH / 4, BB), blk(256);

    conv_mma<2, NFC, false, false, true><<<grid, blk, SMEMSZ>>>(xin, (const uint4*)(wp + off0), b_first, nullptr, A);
    conv_mma<NFC, NFC, true,  false, true><<<grid, blk, SMEMSZ>>>(A,  (const uint4*)(wp + off1), b1a, nullptr, Bb);
    conv_mma<NFC, NFC, false, true,  true><<<grid, blk, SMEMSZ>>>(Bb, (const uint4*)(wp + off2), b1b, A, A);
    conv_mma<NFC, NFC, true,  false, true><<<grid, blk, SMEMSZ>>>(A,  (const uint4*)(wp + off3), b2a, nullptr, Bb);
    conv_mma<NFC, NFC, false, true,  true><<<grid, blk, SMEMSZ>>>(Bb, (const uint4*)(wp + off4), b2b, A, A);
    conv_mma<NFC, NFC, true,  false, true><<<grid, blk, SMEMSZ>>>(A,  (const uint4*)(wp + off5), b3a, nullptr, Bb);
    conv_mma<NFC, NFC, false, true,  true><<<grid, blk, SMEMSZ>>>(Bb, (const uint4*)(wp + off6), b3b, A, A);
    conv_mma<NFC, COUTF, false, false, false><<<grid, blk, SMEMSZ>>>(A, (const uint4*)(wp + off7), b_out, nullptr, core);

    kpn_kernel<<<dim3(WW / 16, HH / 16, BB), 256>>>(core, data, out);
}